// round 16
// baseline (speedup 1.0000x reference)
#include <cuda_runtime.h>
#include <cuda_bf16.h>
#include <math_constants.h>
#include <cstdint>

#define BATCH 16384
#define NN    50
#define ROWS  (BATCH * NN)        // 819200 = 6400 * 128 exactly
#define LDSP  40                  // padded smem row stride in halves (80B)

typedef unsigned int       u32;
typedef unsigned short     u16;
typedef unsigned long long u64;

// ---------------------------------------------------------------------------
// Static device scratch (no allocations allowed)
// ---------------------------------------------------------------------------
__device__ unsigned char g_mask_user[ROWS];
__device__ unsigned char g_mask_news[ROWS];
__device__ int g_mask_mode;  // 0=uint8, 1=int32, 2=float32
// B (=W) pre-packed in mma.sync .col fragment order:
//   frag[( j*NS + s )*32 + lane] = {b0, b1} for n8-tile j, k16-step s.
//   b0 = pack(W[n][k0], W[n][k0+1]), b1 at k0+8;  n = j*8 + (lane>>2),
//   k0 = s*16 + 2*(lane&3).  hi/lo = bf16 split terms.
__device__ uint2 g_Bfh_u[16 * 8 * 32],  g_Bfl_u[16 * 8 * 32];    // 32KB each
__device__ uint2 g_Bfh_n[16 * 8 * 32],  g_Bfl_n[16 * 8 * 32];
__device__ uint2 g_Bfh_s[16 * 24 * 32], g_Bfl_s[16 * 24 * 32];   // 96KB each
__device__ float g_S_u[ROWS], g_S_n[ROWS], g_S_s[ROWS];          // raw scores

// ---------------------------------------------------------------------------
// Mask dtype sniffing (proven): scan first 64KB as u32 words.
// ---------------------------------------------------------------------------
__global__ void detect_mask_kernel(const unsigned int* __restrict__ w) {
    __shared__ int fF, fU;
    if (threadIdx.x == 0) { fF = 0; fU = 0; }
    __syncthreads();
    int lf = 0, lu = 0;
    for (int i = threadIdx.x; i < 16384; i += 256) {
        unsigned v = w[i];
        if (v == 0x3F800000u) lf = 1;
        else if (v != 0u && v != 1u) lu = 1;
    }
    if (lf) atomicOr(&fF, 1);
    if (lu) atomicOr(&fU, 1);
    __syncthreads();
    if (threadIdx.x == 0) g_mask_mode = fF ? 2 : (fU ? 0 : 1);
}

__global__ void expand_mask_kernel(const void* __restrict__ src,
                                   unsigned char* __restrict__ dst, int n) {
    int i = blockIdx.x * blockDim.x + threadIdx.x;
    if (i >= n) return;
    int m = g_mask_mode;
    unsigned char v;
    if (m == 0)      v = (((const unsigned char*)src)[i] != 0);
    else if (m == 1) v = (((const int*)src)[i] != 0);
    else             v = (((const float*)src)[i] != 0.0f);
    dst[i] = v;
}

// ---------------------------------------------------------------------------
// Pack W into bf16 hi/lo mma-fragment order (see layout comment above).
// ---------------------------------------------------------------------------
__device__ __forceinline__ u32 pack_bf16hi(float a, float b) {
    __nv_bfloat162 h = __float22bfloat162_rn(make_float2(a, b));
    return *reinterpret_cast<u32*>(&h);
}
__device__ __forceinline__ u32 pack_bf16lo(float a, float b) {
    __nv_bfloat16 ha = __float2bfloat16(a), hb = __float2bfloat16(b);
    __nv_bfloat162 l = __float22bfloat162_rn(
        make_float2(a - __bfloat162float(ha), b - __bfloat162float(hb)));
    return *reinterpret_cast<u32*>(&l);
}

__global__ void prep_bfrag_kernel(const float* __restrict__ Wu,
                                  const float* __restrict__ Wn,
                                  const float* __restrict__ Ws) {
    int i = blockIdx.x * blockDim.x + threadIdx.x;
    const float* W; uint2 *fh, *fl; int loc, NS, D;
    if (i < 4096)       { W = Wu; fh = g_Bfh_u; fl = g_Bfl_u; loc = i;        NS = 8;  D = 128; }
    else if (i < 8192)  { W = Wn; fh = g_Bfh_n; fl = g_Bfl_n; loc = i - 4096; NS = 8;  D = 128; }
    else if (i < 20480) { W = Ws; fh = g_Bfh_s; fl = g_Bfl_s; loc = i - 8192; NS = 24; D = 384; }
    else return;
    int lane = loc & 31;
    int s    = (loc >> 5) % NS;
    int j    = loc / (NS * 32);
    int n    = j * 8 + (lane >> 2);
    int k0   = s * 16 + 2 * (lane & 3);
    float v0 = W[n * D + k0],     v1 = W[n * D + k0 + 1];
    float v2 = W[n * D + k0 + 8], v3 = W[n * D + k0 + 9];
    fh[loc] = make_uint2(pack_bf16hi(v0, v1), pack_bf16hi(v2, v3));
    fl[loc] = make_uint2(pack_bf16lo(v0, v1), pack_bf16lo(v2, v3));
}

// ---------------------------------------------------------------------------
// Warp MMA helpers
// ---------------------------------------------------------------------------
__device__ __forceinline__ void ldm4(u32& r0, u32& r1, u32& r2, u32& r3, u32 addr) {
    asm volatile("ldmatrix.sync.aligned.m8n8.x4.shared.b16 {%0,%1,%2,%3}, [%4];"
                 : "=r"(r0), "=r"(r1), "=r"(r2), "=r"(r3) : "r"(addr));
}
__device__ __forceinline__ void hmma(float* c, const u32* a, const u32* b) {
    asm volatile("mma.sync.aligned.m16n8k16.row.col.f32.bf16.bf16.f32 "
                 "{%0,%1,%2,%3}, {%4,%5,%6,%7}, {%8,%9}, {%0,%1,%2,%3};"
                 : "+f"(c[0]), "+f"(c[1]), "+f"(c[2]), "+f"(c[3])
                 : "r"(a[0]), "r"(a[1]), "r"(a[2]), "r"(a[3]),
                   "r"(b[0]), "r"(b[1]));
}

// Fast tanh: 1 - 2/(exp(2x)+1). MUFU-based; abs err ~1e-7 (gate is 1e-3).
__device__ __forceinline__ float tanh_fast(float x) {
    float e = __expf(2.0f * x);
    return 1.0f - 2.0f / (e + 1.0f);
}

__device__ __forceinline__ u32 bits2(__nv_bfloat162 v) {
    return *reinterpret_cast<u32*>(&v);
}

// ---------------------------------------------------------------------------
// Tensor-core GEMM + fused score kernel.
//   CTA tile 128x128, 256 threads = 8 warps (2m x 4n), warp tile 64x32.
//   A: gmem -> bf16 hi/lo split -> smem -> ldmatrix (proven path).
//   B: fragment-packed in gmem (L1/L2-resident), loaded by LDG.64.
//   __launch_bounds__(256, 2) pins regs <= 128 -> 2 CTAs/SM (the round-15
//   regression was regs=134 -> 1 CTA/SM). Cheap per-warp B base pointers.
// ---------------------------------------------------------------------------
template <int D>
__global__ void __launch_bounds__(256, 2)
gemm_score_kernel(const float* __restrict__ x,
                  const uint2* __restrict__ Bfh,
                  const uint2* __restrict__ Bfl,
                  const float* __restrict__ bias,
                  const float* __restrict__ uvec,
                  const float* __restrict__ qvec,
                  float* __restrict__ sraw) {
    constexpr int NS = D / 16;
    __shared__ u16 sAh[128 * LDSP], sAl[128 * LDSP];
    __shared__ float sq[128], sbu[128];
    __shared__ float sred[128][4];

    const int tid = threadIdx.x;
    const int lane = tid & 31, wid = tid >> 5;
    const int wm = wid >> 2, wn = wid & 3;            // 2 x 4 warp grid
    const size_t r0 = (size_t)blockIdx.x * 128;

    if (tid < 128) { sq[tid] = qvec[tid]; sbu[tid] = bias[tid] + uvec[tid]; }

    const u32 ahB = (u32)__cvta_generic_to_shared(sAh);
    const u32 alB = (u32)__cvta_generic_to_shared(sAl);

    // ldmatrix per-lane byte offset for A (proven in rounds 11-12)
    const u32 offA = ((lane & 7) + 8 * ((lane >> 3) & 1)) * (LDSP * 2)
                   + (lane >> 4) * 16;

    // Per-warp B fragment base pointers (j0 = wn*4 + pp*2; sibling at +NS*32).
    // Index step per k16: +32 uint2.
    const uint2* bH0 = Bfh + ((u32)(wn * 4) * NS) * 32 + lane;       // pp=0
    const uint2* bL0 = Bfl + ((u32)(wn * 4) * NS) * 32 + lane;
    const uint2* bH1 = bH0 + (u32)(2 * NS) * 32;                     // pp=1
    const uint2* bL1 = bL0 + (u32)(2 * NS) * 32;

    float acc[4][4][4];
    #pragma unroll
    for (int i = 0; i < 4; ++i)
        #pragma unroll
        for (int j = 0; j < 4; ++j)
            #pragma unroll
            for (int r = 0; r < 4; ++r) acc[i][j][r] = 0.0f;

    // A staging: 2 threads per row, 16 floats each (proven mapping)
    const int arow = tid >> 1;
    const int acol = (tid & 1) * 16;
    const float* Ag = x + (r0 + arow) * D + acol;
    u16* sAhp = sAh + arow * LDSP + acol;
    u16* sAlp = sAl + arow * LDSP + acol;

    const int NC = D / 32;
    for (int kc = 0; kc < NC; ++kc) {
        // --- stage A chunk: fp32 -> bf16 hi/lo split ---
        #pragma unroll
        for (int j = 0; j < 4; ++j) {
            float4 v = *(const float4*)(Ag + kc * 32 + j * 4);
            __nv_bfloat162 h01 = __float22bfloat162_rn(make_float2(v.x, v.y));
            __nv_bfloat162 h23 = __float22bfloat162_rn(make_float2(v.z, v.w));
            float2 f01 = __bfloat1622float2(h01);
            float2 f23 = __bfloat1622float2(h23);
            __nv_bfloat162 l01 = __float22bfloat162_rn(
                make_float2(v.x - f01.x, v.y - f01.y));
            __nv_bfloat162 l23 = __float22bfloat162_rn(
                make_float2(v.z - f23.x, v.w - f23.y));
            *(uint2*)(sAhp + j * 4) = make_uint2(bits2(h01), bits2(h23));
            *(uint2*)(sAlp + j * 4) = make_uint2(bits2(l01), bits2(l23));
        }
        __syncthreads();

        // --- 2 k16 steps of warp MMA ---
        #pragma unroll
        for (int s = 0; s < 2; ++s) {
            const u32 ko = (u32)(kc * 2 + s) * 32;   // uint2 index step
            // B fragment loads first: overlap LDG latency with ldmatrix+HMMA
            uint2 h00 = bH0[ko],            h01v = bH0[(u32)NS * 32 + ko];
            uint2 h10 = bH1[ko],            h11v = bH1[(u32)NS * 32 + ko];
            uint2 l00 = bL0[ko],            l01v = bL0[(u32)NS * 32 + ko];
            uint2 l10 = bL1[ko],            l11v = bL1[(u32)NS * 32 + ko];

            u32 Ah[4][4], Al[4][4];
            #pragma unroll
            for (int mt = 0; mt < 4; ++mt) {
                u32 ad = (u32)(wm * 64 + mt * 16) * (LDSP * 2) + s * 32;
                ldm4(Ah[mt][0], Ah[mt][1], Ah[mt][2], Ah[mt][3], ahB + ad + offA);
                ldm4(Al[mt][0], Al[mt][1], Al[mt][2], Al[mt][3], alB + ad + offA);
            }

            u32 bh0[4] = { h00.x, h00.y, h01v.x, h01v.y };
            u32 bl0[4] = { l00.x, l00.y, l01v.x, l01v.y };
            u32 bh1[4] = { h10.x, h10.y, h11v.x, h11v.y };
            u32 bl1[4] = { l10.x, l10.y, l11v.x, l11v.y };

            // term-major: 8 independent HMMAs between accumulator reuse
            #pragma unroll
            for (int mt = 0; mt < 4; ++mt) {
                hmma(acc[mt][0], Ah[mt], &bh0[0]);
                hmma(acc[mt][1], Ah[mt], &bh0[2]);
            }
            #pragma unroll
            for (int mt = 0; mt < 4; ++mt) {
                hmma(acc[mt][0], Ah[mt], &bl0[0]);
                hmma(acc[mt][1], Ah[mt], &bl0[2]);
            }
            #pragma unroll
            for (int mt = 0; mt < 4; ++mt) {
                hmma(acc[mt][0], Al[mt], &bh0[0]);
                hmma(acc[mt][1], Al[mt], &bh0[2]);
            }
            #pragma unroll
            for (int mt = 0; mt < 4; ++mt) {
                hmma(acc[mt][2], Ah[mt], &bh1[0]);
                hmma(acc[mt][3], Ah[mt], &bh1[2]);
            }
            #pragma unroll
            for (int mt = 0; mt < 4; ++mt) {
                hmma(acc[mt][2], Ah[mt], &bl1[0]);
                hmma(acc[mt][3], Ah[mt], &bl1[2]);
            }
            #pragma unroll
            for (int mt = 0; mt < 4; ++mt) {
                hmma(acc[mt][2], Al[mt], &bh1[0]);
                hmma(acc[mt][3], Al[mt], &bh1[2]);
            }
        }
        __syncthreads();
    }

    // ---- fused score epilogue (proven) ----
    // Thread owns rows wm*64 + mt*16 + (lane>>2) + half*8,
    //            cols wn*32 + nt*8 + 2*(lane&3) (+1).
    #pragma unroll
    for (int mt = 0; mt < 4; ++mt) {
        #pragma unroll
        for (int half = 0; half < 2; ++half) {
            float p = 0.0f;
            #pragma unroll
            for (int nt = 0; nt < 4; ++nt) {
                int h0 = wn * 32 + nt * 8 + 2 * (lane & 3);
                p += sq[h0]     * tanh_fast(acc[mt][nt][half * 2]     + sbu[h0]);
                p += sq[h0 + 1] * tanh_fast(acc[mt][nt][half * 2 + 1] + sbu[h0 + 1]);
            }
            p += __shfl_xor_sync(0xffffffffu, p, 1);
            p += __shfl_xor_sync(0xffffffffu, p, 2);
            if ((lane & 3) == 0)
                sred[wm * 64 + mt * 16 + (lane >> 2) + half * 8][wn] = p;
        }
    }
    __syncthreads();
    if (tid < 128)
        sraw[r0 + tid] = sred[tid][0] + sred[tid][1] + sred[tid][2] + sred[tid][3];
}

// ---------------------------------------------------------------------------
// Masked softmax + weighted sum (proven). One CTA (128 threads) per batch row.
// ---------------------------------------------------------------------------
template <int D>
__global__ void __launch_bounds__(128)
softmax_out_kernel(const float* __restrict__ x,
                   const float* __restrict__ sraw,
                   const unsigned char* __restrict__ mask,
                   float* __restrict__ out) {
    __shared__ float attn[NN];
    const int t = threadIdx.x;
    const int b = blockIdx.x;

    if (t < 32) {
        const float* sb = sraw + (size_t)b * NN;
        const unsigned char* mb = mask + (size_t)b * NN;
        bool v0 = (mb[t] != 0);
        float a0 = v0 ? sb[t] : -CUDART_INF_F;
        bool v1 = false;
        float a1 = -CUDART_INF_F;
        if (t + 32 < NN) { v1 = (mb[t + 32] != 0); a1 = v1 ? sb[t + 32] : -CUDART_INF_F; }
        float mx = fmaxf(a0, a1);
        #pragma unroll
        for (int o = 16; o; o >>= 1)
            mx = fmaxf(mx, __shfl_xor_sync(0xffffffffu, mx, o));
        float e0 = v0 ? __expf(a0 - mx) : 0.0f;
        float e1 = v1 ? __expf(a1 - mx) : 0.0f;
        float su = e0 + e1;
        #pragma unroll
        for (int o = 16; o; o >>= 1)
            su += __shfl_xor_sync(0xffffffffu, su, o);
        float inv = 1.0f / su;
        attn[t] = e0 * inv;
        if (t + 32 < NN) attn[t + 32] = e1 * inv;
    }
    __syncthreads();

    const float* xb = x + (size_t)b * NN * D;
    const int NOUT = D / 128;
    float acc[NOUT];
    #pragma unroll
    for (int c = 0; c < NOUT; ++c) acc[c] = 0.0f;
    #pragma unroll 5
    for (int n = 0; n < NN; ++n) {
        float an = attn[n];
        #pragma unroll
        for (int c = 0; c < NOUT; ++c)
            acc[c] = fmaf(an, xb[(size_t)n * D + t + c * 128], acc[c]);
    }
    #pragma unroll
    for (int c = 0; c < NOUT; ++c)
        out[(size_t)b * D + t + c * 128] = acc[c];
}

// ---------------------------------------------------------------------------
// Launch. Inputs (metadata order):
//  0 users (B,N,128)  1 news (B,N,128)  2 sem (B,N,384)
//  3 user_mask (B,N)  4 news_mask (B,N)
//  5-8 W/b/u/q user   9-12 W/b/u/q news   13-16 W/b/u/q sem
// Output: [agg_users (B,128) | agg_news (B,128) | agg_sem (B,384)] f32
// ncu profiles launch slot 4 -> keep GEMM<384> there.
// ---------------------------------------------------------------------------
extern "C" void kernel_launch(void* const* d_in, const int* in_sizes, int n_in,
                              void* d_out, int out_size) {
    const float* users = (const float*)d_in[0];
    const float* news  = (const float*)d_in[1];
    const float* sem   = (const float*)d_in[2];
    const void*  mu    = d_in[3];
    const void*  mn    = d_in[4];
    const float* W_user = (const float*)d_in[5];
    const float* b_user = (const float*)d_in[6];
    const float* u_user = (const float*)d_in[7];
    const float* q_user = (const float*)d_in[8];
    const float* W_news = (const float*)d_in[9];
    const float* b_news = (const float*)d_in[10];
    const float* u_news = (const float*)d_in[11];
    const float* q_news = (const float*)d_in[12];
    const float* W_sem  = (const float*)d_in[13];
    const float* b_sem  = (const float*)d_in[14];
    const float* u_sem  = (const float*)d_in[15];
    const float* q_sem  = (const float*)d_in[16];
    float* out = (float*)d_out;

    void* p;
    cudaGetSymbolAddress(&p, g_mask_user); unsigned char* gmu = (unsigned char*)p;
    cudaGetSymbolAddress(&p, g_mask_news); unsigned char* gmn = (unsigned char*)p;
    cudaGetSymbolAddress(&p, g_Bfh_u); uint2* bhu = (uint2*)p;
    cudaGetSymbolAddress(&p, g_Bfl_u); uint2* blu = (uint2*)p;
    cudaGetSymbolAddress(&p, g_Bfh_n); uint2* bhn = (uint2*)p;
    cudaGetSymbolAddress(&p, g_Bfl_n); uint2* bln = (uint2*)p;
    cudaGetSymbolAddress(&p, g_Bfh_s); uint2* bhs = (uint2*)p;
    cudaGetSymbolAddress(&p, g_Bfl_s); uint2* bls = (uint2*)p;
    cudaGetSymbolAddress(&p, g_S_u);  float* su = (float*)p;
    cudaGetSymbolAddress(&p, g_S_n);  float* sn = (float*)p;
    cudaGetSymbolAddress(&p, g_S_s);  float* ss = (float*)p;

    const int NBLK = ROWS / 128;   // 6400 GEMM CTAs

    detect_mask_kernel<<<1, 256>>>((const unsigned int*)mu);                   // slot 1
    prep_bfrag_kernel<<<(20480 + 255) / 256, 256>>>(W_user, W_news, W_sem);    // slot 2
    expand_mask_kernel<<<(ROWS + 255) / 256, 256>>>(mu, gmu, ROWS);            // slot 3

    gemm_score_kernel<384><<<NBLK, 256>>>(sem, bhs, bls, b_sem, u_sem, q_sem, ss);      // slot 4 (ncu)
    gemm_score_kernel<128><<<NBLK, 256>>>(users, bhu, blu, b_user, u_user, q_user, su); // slot 5
    gemm_score_kernel<128><<<NBLK, 256>>>(news, bhn, bln, b_news, u_news, q_news, sn);  // slot 6

    expand_mask_kernel<<<(ROWS + 255) / 256, 256>>>(mn, gmn, ROWS);            // slot 7

    softmax_out_kernel<128><<<BATCH, 128>>>(users, su, gmu, out);                       // 8
    softmax_out_kernel<128><<<BATCH, 128>>>(news,  sn, gmn, out + (size_t)BATCH * 128); // 9
    softmax_out_kernel<384><<<BATCH, 128>>>(sem,   ss, gmn, out + (size_t)BATCH * 256); // 10
}

// round 17
// speedup vs baseline: 1.5693x; 1.5693x over previous
#include <cuda_runtime.h>
#include <cuda_bf16.h>
#include <math_constants.h>
#include <cstdint>

#define BATCH 16384
#define NN    50
#define ROWS  (BATCH * NN)        // 819200 = 6400 * 128 exactly
#define LDSP  40                  // padded smem row stride in halves (80B)

typedef unsigned int       u32;
typedef unsigned short     u16;
typedef unsigned long long u64;

// ---------------------------------------------------------------------------
// Static device scratch (no allocations allowed)
// ---------------------------------------------------------------------------
__device__ unsigned char g_mask_user[ROWS];
__device__ unsigned char g_mask_news[ROWS];
__device__ int g_mask_mode;  // 0=uint8, 1=int32, 2=float32
// B (=W) pre-packed in mma.sync .col fragment order:
//   frag[( j*NS + s )*32 + lane] = {b0, b1} for n8-tile j, k16-step s.
//   b0 = pack(W[n][k0], W[n][k0+1]), b1 at k0+8;  n = j*8 + (lane>>2),
//   k0 = s*16 + 2*(lane&3).  hi/lo = bf16 split terms.
__device__ uint2 g_Bfh_u[16 * 8 * 32],  g_Bfl_u[16 * 8 * 32];    // 32KB each
__device__ uint2 g_Bfh_n[16 * 8 * 32],  g_Bfl_n[16 * 8 * 32];
__device__ uint2 g_Bfh_s[16 * 24 * 32], g_Bfl_s[16 * 24 * 32];   // 96KB each
__device__ float g_S_u[ROWS], g_S_n[ROWS], g_S_s[ROWS];          // raw scores

// ---------------------------------------------------------------------------
// Mask dtype sniffing (proven): scan first 64KB as u32 words.
// ---------------------------------------------------------------------------
__global__ void detect_mask_kernel(const unsigned int* __restrict__ w) {
    __shared__ int fF, fU;
    if (threadIdx.x == 0) { fF = 0; fU = 0; }
    __syncthreads();
    int lf = 0, lu = 0;
    for (int i = threadIdx.x; i < 16384; i += 256) {
        unsigned v = w[i];
        if (v == 0x3F800000u) lf = 1;
        else if (v != 0u && v != 1u) lu = 1;
    }
    if (lf) atomicOr(&fF, 1);
    if (lu) atomicOr(&fU, 1);
    __syncthreads();
    if (threadIdx.x == 0) g_mask_mode = fF ? 2 : (fU ? 0 : 1);
}

__global__ void expand_mask_kernel(const void* __restrict__ src,
                                   unsigned char* __restrict__ dst, int n) {
    int i = blockIdx.x * blockDim.x + threadIdx.x;
    if (i >= n) return;
    int m = g_mask_mode;
    unsigned char v;
    if (m == 0)      v = (((const unsigned char*)src)[i] != 0);
    else if (m == 1) v = (((const int*)src)[i] != 0);
    else             v = (((const float*)src)[i] != 0.0f);
    dst[i] = v;
}

// ---------------------------------------------------------------------------
// Pack W into bf16 hi/lo mma-fragment order (see layout comment above).
// ---------------------------------------------------------------------------
__device__ __forceinline__ u32 pack_bf16hi(float a, float b) {
    __nv_bfloat162 h = __float22bfloat162_rn(make_float2(a, b));
    return *reinterpret_cast<u32*>(&h);
}
__device__ __forceinline__ u32 pack_bf16lo(float a, float b) {
    __nv_bfloat16 ha = __float2bfloat16(a), hb = __float2bfloat16(b);
    __nv_bfloat162 l = __float22bfloat162_rn(
        make_float2(a - __bfloat162float(ha), b - __bfloat162float(hb)));
    return *reinterpret_cast<u32*>(&l);
}

__global__ void prep_bfrag_kernel(const float* __restrict__ Wu,
                                  const float* __restrict__ Wn,
                                  const float* __restrict__ Ws) {
    int i = blockIdx.x * blockDim.x + threadIdx.x;
    const float* W; uint2 *fh, *fl; int loc, NS, D;
    if (i < 4096)       { W = Wu; fh = g_Bfh_u; fl = g_Bfl_u; loc = i;        NS = 8;  D = 128; }
    else if (i < 8192)  { W = Wn; fh = g_Bfh_n; fl = g_Bfl_n; loc = i - 4096; NS = 8;  D = 128; }
    else if (i < 20480) { W = Ws; fh = g_Bfh_s; fl = g_Bfl_s; loc = i - 8192; NS = 24; D = 384; }
    else return;
    int lane = loc & 31;
    int s    = (loc >> 5) % NS;
    int j    = loc / (NS * 32);
    int n    = j * 8 + (lane >> 2);
    int k0   = s * 16 + 2 * (lane & 3);
    float v0 = W[n * D + k0],     v1 = W[n * D + k0 + 1];
    float v2 = W[n * D + k0 + 8], v3 = W[n * D + k0 + 9];
    fh[loc] = make_uint2(pack_bf16hi(v0, v1), pack_bf16hi(v2, v3));
    fl[loc] = make_uint2(pack_bf16lo(v0, v1), pack_bf16lo(v2, v3));
}

// ---------------------------------------------------------------------------
// Warp MMA helpers
// ---------------------------------------------------------------------------
__device__ __forceinline__ void ldm4(u32& r0, u32& r1, u32& r2, u32& r3, u32 addr) {
    asm volatile("ldmatrix.sync.aligned.m8n8.x4.shared.b16 {%0,%1,%2,%3}, [%4];"
                 : "=r"(r0), "=r"(r1), "=r"(r2), "=r"(r3) : "r"(addr));
}
__device__ __forceinline__ void hmma(float* c, const u32* a, const u32* b) {
    asm volatile("mma.sync.aligned.m16n8k16.row.col.f32.bf16.bf16.f32 "
                 "{%0,%1,%2,%3}, {%4,%5,%6,%7}, {%8,%9}, {%0,%1,%2,%3};"
                 : "+f"(c[0]), "+f"(c[1]), "+f"(c[2]), "+f"(c[3])
                 : "r"(a[0]), "r"(a[1]), "r"(a[2]), "r"(a[3]),
                   "r"(b[0]), "r"(b[1]));
}

// Fast tanh: 1 - 2/(exp(2x)+1). MUFU-based; abs err ~1e-7 (gate is 1e-3).
__device__ __forceinline__ float tanh_fast(float x) {
    float e = __expf(2.0f * x);
    return 1.0f - 2.0f / (e + 1.0f);
}

__device__ __forceinline__ u32 bits2(__nv_bfloat162 v) {
    return *reinterpret_cast<u32*>(&v);
}

// ---------------------------------------------------------------------------
// Tensor-core GEMM + fused score kernel (v4: register-lean).
//   CTA tile 128x128, 256 threads = 8 warps (2m x 4n), warp tile 64x32.
//   A: gmem -> bf16 hi/lo split -> smem -> ldmatrix, but hi and lo are
//      processed SEQUENTIALLY, reusing the same 16 fragment registers:
//      live regs ~= 64 acc + 16 A + 16 B + misc ~= 115 -> fits (256,2)
//      with NO ptxas spills (round-16 regression: pinned 128 = spill traffic).
//   B: fragment-packed in gmem (L1/L2-resident), LDG.64 at s-top so load
//      latency hides under ldmatrix + early HMMAs.
// ---------------------------------------------------------------------------
template <int D>
__global__ void __launch_bounds__(256, 2)
gemm_score_kernel(const float* __restrict__ x,
                  const uint2* __restrict__ Bfh,
                  const uint2* __restrict__ Bfl,
                  const float* __restrict__ bias,
                  const float* __restrict__ uvec,
                  const float* __restrict__ qvec,
                  float* __restrict__ sraw) {
    constexpr int NS = D / 16;
    __shared__ u16 sAh[128 * LDSP], sAl[128 * LDSP];
    __shared__ float sq[128], sbu[128];
    __shared__ float sred[128][4];

    const int tid = threadIdx.x;
    const int lane = tid & 31, wid = tid >> 5;
    const int wm = wid >> 2, wn = wid & 3;            // 2 x 4 warp grid
    const size_t r0 = (size_t)blockIdx.x * 128;

    if (tid < 128) { sq[tid] = qvec[tid]; sbu[tid] = bias[tid] + uvec[tid]; }

    const u32 ahB = (u32)__cvta_generic_to_shared(sAh);
    const u32 alB = (u32)__cvta_generic_to_shared(sAl);

    // ldmatrix per-lane byte offset for A (proven in rounds 11-16)
    const u32 offA = ((lane & 7) + 8 * ((lane >> 3) & 1)) * (LDSP * 2)
                   + (lane >> 4) * 16;

    // Per-warp B fragment base pointers (n8 tiles wn*4 .. wn*4+3).
    const uint2* bB0 = Bfh + ((u32)(wn * 4) * NS) * 32 + lane;
    const uint2* bL0 = Bfl + ((u32)(wn * 4) * NS) * 32 + lane;

    float acc[4][4][4];
    #pragma unroll
    for (int i = 0; i < 4; ++i)
        #pragma unroll
        for (int j = 0; j < 4; ++j)
            #pragma unroll
            for (int r = 0; r < 4; ++r) acc[i][j][r] = 0.0f;

    // A staging: 2 threads per row, 16 floats each (proven mapping)
    const int arow = tid >> 1;
    const int acol = (tid & 1) * 16;
    const float* Ag = x + (r0 + arow) * D + acol;
    u16* sAhp = sAh + arow * LDSP + acol;
    u16* sAlp = sAl + arow * LDSP + acol;

    const int NC = D / 32;
    for (int kc = 0; kc < NC; ++kc) {
        // --- stage A chunk: fp32 -> bf16 hi/lo split ---
        #pragma unroll
        for (int j = 0; j < 4; ++j) {
            float4 v = *(const float4*)(Ag + kc * 32 + j * 4);
            __nv_bfloat162 h01 = __float22bfloat162_rn(make_float2(v.x, v.y));
            __nv_bfloat162 h23 = __float22bfloat162_rn(make_float2(v.z, v.w));
            float2 f01 = __bfloat1622float2(h01);
            float2 f23 = __bfloat1622float2(h23);
            __nv_bfloat162 l01 = __float22bfloat162_rn(
                make_float2(v.x - f01.x, v.y - f01.y));
            __nv_bfloat162 l23 = __float22bfloat162_rn(
                make_float2(v.z - f23.x, v.w - f23.y));
            *(uint2*)(sAhp + j * 4) = make_uint2(bits2(h01), bits2(h23));
            *(uint2*)(sAlp + j * 4) = make_uint2(bits2(l01), bits2(l23));
        }
        __syncthreads();

        // --- 2 k16 steps of warp MMA ---
        #pragma unroll
        for (int s = 0; s < 2; ++s) {
            const u32 ko = (u32)(kc * 2 + s) * 32;   // uint2 index step
            // B fragment loads first (latency hidden under ldmatrix/HMMA)
            uint2 h00 = bB0[ko];
            uint2 h01v = bB0[(u32)NS * 32 + ko];
            uint2 h10 = bB0[(u32)(2 * NS) * 32 + ko];
            uint2 h11v = bB0[(u32)(3 * NS) * 32 + ko];
            uint2 l00 = bL0[ko];
            uint2 l01v = bL0[(u32)NS * 32 + ko];
            uint2 l10 = bL0[(u32)(2 * NS) * 32 + ko];
            uint2 l11v = bL0[(u32)(3 * NS) * 32 + ko];
            u32 bh0[4] = { h00.x, h00.y, h01v.x, h01v.y };
            u32 bh1[4] = { h10.x, h10.y, h11v.x, h11v.y };
            u32 bl0[4] = { l00.x, l00.y, l01v.x, l01v.y };
            u32 bl1[4] = { l10.x, l10.y, l11v.x, l11v.y };

            u32 A[4][4];                              // reused for Ah then Al
            const u32 sbase = s * 32 + offA;

            // --- Ah phase: 32 HMMAs (AhBh + AhBl over both n-pairs) ---
            #pragma unroll
            for (int mt = 0; mt < 4; ++mt) {
                u32 ad = (u32)(wm * 64 + mt * 16) * (LDSP * 2) + sbase;
                ldm4(A[mt][0], A[mt][1], A[mt][2], A[mt][3], ahB + ad);
            }
            #pragma unroll
            for (int mt = 0; mt < 4; ++mt) {
                hmma(acc[mt][0], A[mt], &bh0[0]);
                hmma(acc[mt][1], A[mt], &bh0[2]);
            }
            #pragma unroll
            for (int mt = 0; mt < 4; ++mt) {
                hmma(acc[mt][2], A[mt], &bh1[0]);
                hmma(acc[mt][3], A[mt], &bh1[2]);
            }
            #pragma unroll
            for (int mt = 0; mt < 4; ++mt) {
                hmma(acc[mt][0], A[mt], &bl0[0]);
                hmma(acc[mt][1], A[mt], &bl0[2]);
            }
            #pragma unroll
            for (int mt = 0; mt < 4; ++mt) {
                hmma(acc[mt][2], A[mt], &bl1[0]);
                hmma(acc[mt][3], A[mt], &bl1[2]);
            }

            // --- Al phase: reload A regs, 16 HMMAs (AlBh) ---
            #pragma unroll
            for (int mt = 0; mt < 4; ++mt) {
                u32 ad = (u32)(wm * 64 + mt * 16) * (LDSP * 2) + sbase;
                ldm4(A[mt][0], A[mt][1], A[mt][2], A[mt][3], alB + ad);
            }
            #pragma unroll
            for (int mt = 0; mt < 4; ++mt) {
                hmma(acc[mt][0], A[mt], &bh0[0]);
                hmma(acc[mt][1], A[mt], &bh0[2]);
            }
            #pragma unroll
            for (int mt = 0; mt < 4; ++mt) {
                hmma(acc[mt][2], A[mt], &bh1[0]);
                hmma(acc[mt][3], A[mt], &bh1[2]);
            }
        }
        __syncthreads();
    }

    // ---- fused score epilogue (proven) ----
    // Thread owns rows wm*64 + mt*16 + (lane>>2) + half*8,
    //            cols wn*32 + nt*8 + 2*(lane&3) (+1).
    #pragma unroll
    for (int mt = 0; mt < 4; ++mt) {
        #pragma unroll
        for (int half = 0; half < 2; ++half) {
            float p = 0.0f;
            #pragma unroll
            for (int nt = 0; nt < 4; ++nt) {
                int h0 = wn * 32 + nt * 8 + 2 * (lane & 3);
                p += sq[h0]     * tanh_fast(acc[mt][nt][half * 2]     + sbu[h0]);
                p += sq[h0 + 1] * tanh_fast(acc[mt][nt][half * 2 + 1] + sbu[h0 + 1]);
            }
            p += __shfl_xor_sync(0xffffffffu, p, 1);
            p += __shfl_xor_sync(0xffffffffu, p, 2);
            if ((lane & 3) == 0)
                sred[wm * 64 + mt * 16 + (lane >> 2) + half * 8][wn] = p;
        }
    }
    __syncthreads();
    if (tid < 128)
        sraw[r0 + tid] = sred[tid][0] + sred[tid][1] + sred[tid][2] + sred[tid][3];
}

// ---------------------------------------------------------------------------
// Masked softmax + weighted sum (proven). One CTA (128 threads) per batch row.
// ---------------------------------------------------------------------------
template <int D>
__global__ void __launch_bounds__(128)
softmax_out_kernel(const float* __restrict__ x,
                   const float* __restrict__ sraw,
                   const unsigned char* __restrict__ mask,
                   float* __restrict__ out) {
    __shared__ float attn[NN];
    const int t = threadIdx.x;
    const int b = blockIdx.x;

    if (t < 32) {
        const float* sb = sraw + (size_t)b * NN;
        const unsigned char* mb = mask + (size_t)b * NN;
        bool v0 = (mb[t] != 0);
        float a0 = v0 ? sb[t] : -CUDART_INF_F;
        bool v1 = false;
        float a1 = -CUDART_INF_F;
        if (t + 32 < NN) { v1 = (mb[t + 32] != 0); a1 = v1 ? sb[t + 32] : -CUDART_INF_F; }
        float mx = fmaxf(a0, a1);
        #pragma unroll
        for (int o = 16; o; o >>= 1)
            mx = fmaxf(mx, __shfl_xor_sync(0xffffffffu, mx, o));
        float e0 = v0 ? __expf(a0 - mx) : 0.0f;
        float e1 = v1 ? __expf(a1 - mx) : 0.0f;
        float su = e0 + e1;
        #pragma unroll
        for (int o = 16; o; o >>= 1)
            su += __shfl_xor_sync(0xffffffffu, su, o);
        float inv = 1.0f / su;
        attn[t] = e0 * inv;
        if (t + 32 < NN) attn[t + 32] = e1 * inv;
    }
    __syncthreads();

    const float* xb = x + (size_t)b * NN * D;
    const int NOUT = D / 128;
    float acc[NOUT];
    #pragma unroll
    for (int c = 0; c < NOUT; ++c) acc[c] = 0.0f;
    #pragma unroll 5
    for (int n = 0; n < NN; ++n) {
        float an = attn[n];
        #pragma unroll
        for (int c = 0; c < NOUT; ++c)
            acc[c] = fmaf(an, xb[(size_t)n * D + t + c * 128], acc[c]);
    }
    #pragma unroll
    for (int c = 0; c < NOUT; ++c)
        out[(size_t)b * D + t + c * 128] = acc[c];
}

// ---------------------------------------------------------------------------
// Launch. Inputs (metadata order):
//  0 users (B,N,128)  1 news (B,N,128)  2 sem (B,N,384)
//  3 user_mask (B,N)  4 news_mask (B,N)
//  5-8 W/b/u/q user   9-12 W/b/u/q news   13-16 W/b/u/q sem
// Output: [agg_users (B,128) | agg_news (B,128) | agg_sem (B,384)] f32
// ncu profiles launch slot 4 -> keep GEMM<384> there.
// ---------------------------------------------------------------------------
extern "C" void kernel_launch(void* const* d_in, const int* in_sizes, int n_in,
                              void* d_out, int out_size) {
    const float* users = (const float*)d_in[0];
    const float* news  = (const float*)d_in[1];
    const float* sem   = (const float*)d_in[2];
    const void*  mu    = d_in[3];
    const void*  mn    = d_in[4];
    const float* W_user = (const float*)d_in[5];
    const float* b_user = (const float*)d_in[6];
    const float* u_user = (const float*)d_in[7];
    const float* q_user = (const float*)d_in[8];
    const float* W_news = (const float*)d_in[9];
    const float* b_news = (const float*)d_in[10];
    const float* u_news = (const float*)d_in[11];
    const float* q_news = (const float*)d_in[12];
    const float* W_sem  = (const float*)d_in[13];
    const float* b_sem  = (const float*)d_in[14];
    const float* u_sem  = (const float*)d_in[15];
    const float* q_sem  = (const float*)d_in[16];
    float* out = (float*)d_out;

    void* p;
    cudaGetSymbolAddress(&p, g_mask_user); unsigned char* gmu = (unsigned char*)p;
    cudaGetSymbolAddress(&p, g_mask_news); unsigned char* gmn = (unsigned char*)p;
    cudaGetSymbolAddress(&p, g_Bfh_u); uint2* bhu = (uint2*)p;
    cudaGetSymbolAddress(&p, g_Bfl_u); uint2* blu = (uint2*)p;
    cudaGetSymbolAddress(&p, g_Bfh_n); uint2* bhn = (uint2*)p;
    cudaGetSymbolAddress(&p, g_Bfl_n); uint2* bln = (uint2*)p;
    cudaGetSymbolAddress(&p, g_Bfh_s); uint2* bhs = (uint2*)p;
    cudaGetSymbolAddress(&p, g_Bfl_s); uint2* bls = (uint2*)p;
    cudaGetSymbolAddress(&p, g_S_u);  float* su = (float*)p;
    cudaGetSymbolAddress(&p, g_S_n);  float* sn = (float*)p;
    cudaGetSymbolAddress(&p, g_S_s);  float* ss = (float*)p;

    const int NBLK = ROWS / 128;   // 6400 GEMM CTAs

    detect_mask_kernel<<<1, 256>>>((const unsigned int*)mu);                   // slot 1
    prep_bfrag_kernel<<<(20480 + 255) / 256, 256>>>(W_user, W_news, W_sem);    // slot 2
    expand_mask_kernel<<<(ROWS + 255) / 256, 256>>>(mu, gmu, ROWS);            // slot 3

    gemm_score_kernel<384><<<NBLK, 256>>>(sem, bhs, bls, b_sem, u_sem, q_sem, ss);      // slot 4 (ncu)
    gemm_score_kernel<128><<<NBLK, 256>>>(users, bhu, blu, b_user, u_user, q_user, su); // slot 5
    gemm_score_kernel<128><<<NBLK, 256>>>(news, bhn, bln, b_news, u_news, q_news, sn);  // slot 6

    expand_mask_kernel<<<(ROWS + 255) / 256, 256>>>(mn, gmn, ROWS);            // slot 7

    softmax_out_kernel<128><<<BATCH, 128>>>(users, su, gmu, out);                       // 8
    softmax_out_kernel<128><<<BATCH, 128>>>(news,  sn, gmn, out + (size_t)BATCH * 128); // 9
    softmax_out_kernel<384><<<BATCH, 128>>>(sem,   ss, gmn, out + (size_t)BATCH * 256); // 10
}